// round 2
// baseline (speedup 1.0000x reference)
#include <cuda_runtime.h>
#include <math.h>

// ---------------------------------------------------------------------------
// Problem constants: B=2, T=2048, D=1024, H=16, hd=64
// Algebra: out = softmax(QK^T/8) @ V @ (rope^T rope) -> fold M=rope^T rope into Wv.
// ---------------------------------------------------------------------------
#define BB 2
#define TT 2048
#define DD 1024
#define HH 16
#define HD 64
#define MROWS (BB * TT)   // 4096

// Scratch (device globals; no allocation allowed)
__device__ float g_Q[MROWS * DD];
__device__ float g_K[MROWS * DD];
__device__ float g_V[MROWS * DD];
__device__ float g_O[MROWS * DD];
__device__ float g_rope[TT * HD];
__device__ float g_M[HD * HD];
__device__ float g_Wv2[DD * DD];

// ---------------------------------------------------------------------------
// rope[s,d] : d<32 -> cos(s*invf[d]), d>=32 -> sin(s*invf[d-32])
// double trig of the fp32 angle: matches jnp fp32 semantics, fast-math safe.
// ---------------------------------------------------------------------------
__global__ void rope_kernel(float* __restrict__ rope) {
    int s = blockIdx.x;
    int d = threadIdx.x;
    int dd = (d < 32) ? d : d - 32;
    double invf = exp(-((double)dd / 32.0) * log(10000.0));
    float ang = (float)s * (float)invf;        // fp32 product like the reference
    double a = (double)ang;
    rope[s * HD + d] = (d < 32) ? (float)cos(a) : (float)sin(a);
}

// M = rope^T @ rope  (64x64)
__global__ void m_kernel(const float* __restrict__ rope, float* __restrict__ Mm) {
    int i = blockIdx.x;    // 64
    int j = threadIdx.x;   // 64
    float acc = 0.f;
    for (int s = 0; s < TT; s++)
        acc += rope[s * HD + i] * rope[s * HD + j];
    Mm[i * HD + j] = acc;
}

// Wv2 = Wv @ blockdiag(M) per head
__global__ void fold_wv_kernel(const float* __restrict__ Wv,
                               const float* __restrict__ Mm,
                               float* __restrict__ Wv2) {
    __shared__ float Ms[HD * HD];
    for (int t = threadIdx.x; t < HD * HD; t += 256) Ms[t] = Mm[t];
    __syncthreads();
    int idx = blockIdx.x * 256 + threadIdx.x;   // 0 .. 1024*1024-1
    int r = idx >> 10;
    int c = idx & 1023;
    int h = c >> 6;
    int j = c & 63;
    const float* w = Wv + r * DD + h * HD;
    float acc = 0.f;
#pragma unroll 16
    for (int i = 0; i < HD; i++)
        acc += w[i] * Ms[i * HD + j];
    Wv2[idx] = acc;
}

// ---------------------------------------------------------------------------
// SGEMM: C[M,N] = A[M,K] @ B[K,N] (+ bias). 128x128 tile, BK=8, 256 thr, 8x8.
// Shapes used here: M=4096, N=1024, K=1024 (all tile-divisible).
// ---------------------------------------------------------------------------
__global__ __launch_bounds__(256) void sgemm128(const float* __restrict__ A,
                                                const float* __restrict__ B,
                                                const float* __restrict__ bias,
                                                float* __restrict__ C,
                                                int M, int N, int K) {
    __shared__ float As[8][128];
    __shared__ float Bs[8][128];
    int tid = threadIdx.x;
    int tx = tid & 15;        // 0..15
    int ty = tid >> 4;        // 0..15
    int aRow = tid >> 1;          // 0..127
    int aCol = (tid & 1) * 4;     // 0 or 4
    int bRow = tid >> 5;          // 0..7
    int bCol = (tid & 31) * 4;    // 0..124

    const float* Ap = A + (size_t)(blockIdx.y * 128 + aRow) * K + aCol;
    const float* Bp = B + (size_t)bRow * N + blockIdx.x * 128 + bCol;

    float acc[8][8];
#pragma unroll
    for (int i = 0; i < 8; i++)
#pragma unroll
        for (int j = 0; j < 8; j++) acc[i][j] = 0.f;

    for (int k0 = 0; k0 < K; k0 += 8) {
        float4 av = *(const float4*)Ap;
        float4 bv = *(const float4*)Bp;
        As[aCol + 0][aRow] = av.x;
        As[aCol + 1][aRow] = av.y;
        As[aCol + 2][aRow] = av.z;
        As[aCol + 3][aRow] = av.w;
        *(float4*)&Bs[bRow][bCol] = bv;
        __syncthreads();
#pragma unroll
        for (int kk = 0; kk < 8; kk++) {
            float4 a0 = *(const float4*)&As[kk][ty * 8];
            float4 a1 = *(const float4*)&As[kk][ty * 8 + 4];
            float4 b0 = *(const float4*)&Bs[kk][tx * 8];
            float4 b1 = *(const float4*)&Bs[kk][tx * 8 + 4];
            float ra[8] = {a0.x, a0.y, a0.z, a0.w, a1.x, a1.y, a1.z, a1.w};
            float rb[8] = {b0.x, b0.y, b0.z, b0.w, b1.x, b1.y, b1.z, b1.w};
#pragma unroll
            for (int i = 0; i < 8; i++)
#pragma unroll
                for (int j = 0; j < 8; j++)
                    acc[i][j] += ra[i] * rb[j];
        }
        __syncthreads();
        Ap += 8;
        Bp += (size_t)8 * N;
    }

    int cRow = blockIdx.y * 128 + ty * 8;
    int cCol = blockIdx.x * 128 + tx * 8;
    float bvals[8];
#pragma unroll
    for (int j = 0; j < 8; j++) bvals[j] = bias ? bias[cCol + j] : 0.f;
#pragma unroll
    for (int i = 0; i < 8; i++) {
        float4 v0, v1;
        v0.x = acc[i][0] + bvals[0];
        v0.y = acc[i][1] + bvals[1];
        v0.z = acc[i][2] + bvals[2];
        v0.w = acc[i][3] + bvals[3];
        v1.x = acc[i][4] + bvals[4];
        v1.y = acc[i][5] + bvals[5];
        v1.z = acc[i][6] + bvals[6];
        v1.w = acc[i][7] + bvals[7];
        float* cp = C + (size_t)(cRow + i) * N + cCol;
        *(float4*)cp = v0;
        *(float4*)(cp + 4) = v1;
    }
}

// ---------------------------------------------------------------------------
// Flash attention, fp32. Grid (qtile=32, bh=32). Block 256 threads.
// 64 q-rows per block, 64-wide kv tiles, online softmax.
// smem: Qt[d][i], Kt[d][m], Vs[m][d], St[m][i]  (stride 68 for 16B alignment)
// ---------------------------------------------------------------------------
#define ATP 68
#define FLASH_SMEM ((4 * 64 * ATP + 3 * 64 + 256) * sizeof(float))

__global__ __launch_bounds__(256) void flash_kernel(const float* __restrict__ Qg,
                                                    const float* __restrict__ Kg,
                                                    const float* __restrict__ Vg,
                                                    float* __restrict__ Og) {
    extern __shared__ float sm[];
    float* Qt = sm;                    // [d][i]
    float* Kt = Qt + 64 * ATP;         // [d][m]
    float* Vs = Kt + 64 * ATP;         // [m][d]
    float* St = Vs + 64 * ATP;         // [m][i]
    float* mrow = St + 64 * ATP;       // 64
    float* lrow = mrow + 64;           // 64
    float* arow = lrow + 64;           // 64
    float* red = arow + 64;            // 256

    int tid = threadIdx.x;
    int tx = tid & 15;
    int ty = tid >> 4;
    int qt = blockIdx.x;
    int bh = blockIdx.y;
    int b = bh >> 4;
    int h = bh & 15;
    int qRowBase = b * TT + qt * 64;
    int colBase = h * HD;

    // load Q tile transposed into Qt[d][i]
    {
        int r = tid >> 4;
        int c4 = (tid & 15) * 4;
#pragma unroll
        for (int l = 0; l < 4; l++) {
            int rr = r + l * 16;
            float4 v = *(const float4*)&Qg[(size_t)(qRowBase + rr) * DD + colBase + c4];
            Qt[(c4 + 0) * ATP + rr] = v.x;
            Qt[(c4 + 1) * ATP + rr] = v.y;
            Qt[(c4 + 2) * ATP + rr] = v.z;
            Qt[(c4 + 3) * ATP + rr] = v.w;
        }
    }
    if (tid < 64) {
        mrow[tid] = -INFINITY;
        lrow[tid] = 0.f;
    }

    float o[4][4];
#pragma unroll
    for (int i = 0; i < 4; i++)
#pragma unroll
        for (int j = 0; j < 4; j++) o[i][j] = 0.f;

    int si = tid >> 2;   // softmax row 0..63
    int sp = tid & 3;    // part 0..3

    for (int j = 0; j < TT / 64; j++) {
        __syncthreads();  // prior tile consumption done
        // load K (transposed) + V (direct)
        {
            int r = tid >> 4;
            int c4 = (tid & 15) * 4;
            int kRowBase = b * TT + j * 64;
#pragma unroll
            for (int l = 0; l < 4; l++) {
                int rr = r + l * 16;
                float4 kv = *(const float4*)&Kg[(size_t)(kRowBase + rr) * DD + colBase + c4];
                Kt[(c4 + 0) * ATP + rr] = kv.x;
                Kt[(c4 + 1) * ATP + rr] = kv.y;
                Kt[(c4 + 2) * ATP + rr] = kv.z;
                Kt[(c4 + 3) * ATP + rr] = kv.w;
                float4 vv = *(const float4*)&Vg[(size_t)(kRowBase + rr) * DD + colBase + c4];
                *(float4*)&Vs[rr * ATP + c4] = vv;
            }
        }
        __syncthreads();

        // S = Q @ K^T (this thread: rows ty*4.., cols tx*4..)
        float s[4][4];
#pragma unroll
        for (int i = 0; i < 4; i++)
#pragma unroll
            for (int c = 0; c < 4; c++) s[i][c] = 0.f;
#pragma unroll 8
        for (int d = 0; d < HD; d++) {
            float4 q = *(const float4*)&Qt[d * ATP + ty * 4];
            float4 k = *(const float4*)&Kt[d * ATP + tx * 4];
            s[0][0] += q.x * k.x; s[0][1] += q.x * k.y; s[0][2] += q.x * k.z; s[0][3] += q.x * k.w;
            s[1][0] += q.y * k.x; s[1][1] += q.y * k.y; s[1][2] += q.y * k.z; s[1][3] += q.y * k.w;
            s[2][0] += q.z * k.x; s[2][1] += q.z * k.y; s[2][2] += q.z * k.z; s[2][3] += q.z * k.w;
            s[3][0] += q.w * k.x; s[3][1] += q.w * k.y; s[3][2] += q.w * k.z; s[3][3] += q.w * k.w;
        }
        // scale and write transposed to St[m][i]
#pragma unroll
        for (int c = 0; c < 4; c++) {
            float4 v;
            v.x = s[0][c] * 0.125f;
            v.y = s[1][c] * 0.125f;
            v.z = s[2][c] * 0.125f;
            v.w = s[3][c] * 0.125f;
            *(float4*)&St[(tx * 4 + c) * ATP + ty * 4] = v;
        }
        __syncthreads();

        // online softmax: 4 threads per row
        float pm = -INFINITY;
#pragma unroll
        for (int t = 0; t < 16; t++)
            pm = fmaxf(pm, St[(sp * 16 + t) * ATP + si]);
        red[si * 4 + sp] = pm;
        __syncthreads();
        if (sp == 0) {
            float mo = mrow[si];
            float mn = fmaxf(fmaxf(red[si * 4], red[si * 4 + 1]),
                             fmaxf(red[si * 4 + 2], red[si * 4 + 3]));
            mn = fmaxf(mo, mn);
            mrow[si] = mn;
            arow[si] = expf(mo - mn);
        }
        __syncthreads();
        {
            float mn = mrow[si];
            float ps = 0.f;
#pragma unroll
            for (int t = 0; t < 16; t++) {
                int m = sp * 16 + t;
                float p = expf(St[m * ATP + si] - mn);
                St[m * ATP + si] = p;
                ps += p;
            }
            red[si * 4 + sp] = ps;
        }
        __syncthreads();
        if (sp == 0)
            lrow[si] = arow[si] * lrow[si] +
                       red[si * 4] + red[si * 4 + 1] + red[si * 4 + 2] + red[si * 4 + 3];

        // rescale O by alpha, accumulate P @ V
#pragma unroll
        for (int r2 = 0; r2 < 4; r2++) {
            float a = arow[ty * 4 + r2];
            o[r2][0] *= a; o[r2][1] *= a; o[r2][2] *= a; o[r2][3] *= a;
        }
#pragma unroll 8
        for (int m = 0; m < 64; m++) {
            float4 p = *(const float4*)&St[m * ATP + ty * 4];
            float4 v = *(const float4*)&Vs[m * ATP + tx * 4];
            o[0][0] += p.x * v.x; o[0][1] += p.x * v.y; o[0][2] += p.x * v.z; o[0][3] += p.x * v.w;
            o[1][0] += p.y * v.x; o[1][1] += p.y * v.y; o[1][2] += p.y * v.z; o[1][3] += p.y * v.w;
            o[2][0] += p.z * v.x; o[2][1] += p.z * v.y; o[2][2] += p.z * v.z; o[2][3] += p.z * v.w;
            o[3][0] += p.w * v.x; o[3][1] += p.w * v.y; o[3][2] += p.w * v.z; o[3][3] += p.w * v.w;
        }
    }
    __syncthreads();  // lrow final values visible

#pragma unroll
    for (int r2 = 0; r2 < 4; r2++) {
        int i = ty * 4 + r2;
        float invl = 1.f / lrow[i];
        float4 v;
        v.x = o[r2][0] * invl;
        v.y = o[r2][1] * invl;
        v.z = o[r2][2] * invl;
        v.w = o[r2][3] * invl;
        *(float4*)&Og[(size_t)(qRowBase + i) * DD + colBase + tx * 4] = v;
    }
}

// ---------------------------------------------------------------------------
extern "C" void kernel_launch(void* const* d_in, const int* in_sizes, int n_in,
                              void* d_out, int out_size) {
    (void)in_sizes; (void)n_in; (void)out_size;
    const float* x  = (const float*)d_in[0];
    const float* Wq = (const float*)d_in[1];
    const float* Wk = (const float*)d_in[2];
    const float* Wv = (const float*)d_in[3];
    const float* Wo = (const float*)d_in[4];
    const float* bo = (const float*)d_in[5];
    float* out = (float*)d_out;

    float *Q, *K, *V, *O, *rope, *Mm, *Wv2;
    cudaGetSymbolAddress((void**)&Q, g_Q);
    cudaGetSymbolAddress((void**)&K, g_K);
    cudaGetSymbolAddress((void**)&V, g_V);
    cudaGetSymbolAddress((void**)&O, g_O);
    cudaGetSymbolAddress((void**)&rope, g_rope);
    cudaGetSymbolAddress((void**)&Mm, g_M);
    cudaGetSymbolAddress((void**)&Wv2, g_Wv2);

    rope_kernel<<<TT, HD>>>(rope);
    m_kernel<<<HD, HD>>>(rope, Mm);
    fold_wv_kernel<<<(DD * DD) / 256, 256>>>(Wv, Mm, Wv2);

    dim3 ggrid(DD / 128, MROWS / 128);  // (8, 32)
    sgemm128<<<ggrid, 256>>>(x, Wq, nullptr, Q, MROWS, DD, DD);
    sgemm128<<<ggrid, 256>>>(x, Wk, nullptr, K, MROWS, DD, DD);
    sgemm128<<<ggrid, 256>>>(x, Wv2, nullptr, V, MROWS, DD, DD);

    cudaFuncSetAttribute(flash_kernel, cudaFuncAttributeMaxDynamicSharedMemorySize,
                         (int)FLASH_SMEM);
    flash_kernel<<<dim3(TT / 64, BB * HH), 256, FLASH_SMEM>>>(Q, K, V, O);

    sgemm128<<<ggrid, 256>>>(O, Wo, bo, out, MROWS, DD, DD);
}

// round 4
// speedup vs baseline: 2.7724x; 2.7724x over previous
#include <cuda_runtime.h>
#include <math.h>

// ---------------------------------------------------------------------------
// B=2, T=2048, D=1024, H=16, hd=64
// Algebra: out = softmax(QK^T/8) @ V @ (rope^T rope) -> fold M into Wv.
// All big matmuls on tensor pipe via mma.sync m16n8k8 tf32.
// ---------------------------------------------------------------------------
#define BB 2
#define TT 2048
#define DD 1024
#define HH 16
#define HD 64
#define MROWS (BB * TT)   // 4096

__device__ float g_Q[MROWS * DD];
__device__ float g_K[MROWS * DD];
__device__ float g_V[MROWS * DD];
__device__ float g_O[MROWS * DD];
__device__ float g_rope[TT * HD];
__device__ float g_M[HD * HD];
__device__ float g_Wv2[DD * DD];

// ---------------------------------------------------------------------------
__device__ __forceinline__ unsigned f2tf(float f) {
    unsigned r;
    asm("cvt.rna.tf32.f32 %0, %1;" : "=r"(r) : "f"(f));
    return r;
}

__device__ __forceinline__ void mma_tf32(float* c, const unsigned* a, const unsigned* b) {
    asm volatile(
        "mma.sync.aligned.m16n8k8.row.col.f32.tf32.tf32.f32 "
        "{%0,%1,%2,%3}, {%4,%5,%6,%7}, {%8,%9}, {%0,%1,%2,%3};"
        : "+f"(c[0]), "+f"(c[1]), "+f"(c[2]), "+f"(c[3])
        : "r"(a[0]), "r"(a[1]), "r"(a[2]), "r"(a[3]), "r"(b[0]), "r"(b[1]));
}

// ---------------------------------------------------------------------------
// rope / M / fold (prologue, tiny)
// ---------------------------------------------------------------------------
__global__ void rope_kernel(float* __restrict__ rope) {
    int s = blockIdx.x;
    int d = threadIdx.x;
    int dd = (d < 32) ? d : d - 32;
    double invf = exp(-((double)dd / 32.0) * log(10000.0));
    float ang = (float)s * (float)invf;
    double a = (double)ang;
    rope[s * HD + d] = (d < 32) ? (float)cos(a) : (float)sin(a);
}

__global__ void m_kernel(const float* __restrict__ rope, float* __restrict__ Mm) {
    int i = blockIdx.x;
    int j = threadIdx.x;
    float acc = 0.f;
    for (int s = 0; s < TT; s++)
        acc += rope[s * HD + i] * rope[s * HD + j];
    Mm[i * HD + j] = acc;
}

__global__ void fold_wv_kernel(const float* __restrict__ Wv,
                               const float* __restrict__ Mm,
                               float* __restrict__ Wv2) {
    __shared__ float Ms[HD * HD];
    for (int t = threadIdx.x; t < HD * HD; t += 256) Ms[t] = Mm[t];
    __syncthreads();
    int idx = blockIdx.x * 256 + threadIdx.x;
    int r = idx >> 10;
    int c = idx & 1023;
    int h = c >> 6;
    int j = c & 63;
    const float* w = Wv + r * DD + h * HD;
    float acc = 0.f;
#pragma unroll 16
    for (int i = 0; i < HD; i++)
        acc += w[i] * Ms[i * HD + j];
    Wv2[idx] = acc;
}

// ---------------------------------------------------------------------------
// tf32 tensor-core GEMM: C[M,N] = A[M,K] @ B[K,N] (+bias)
// Block 128x128, BK=32, 256 threads (8 warps as 4m x 2n, warptile 32x64).
// As row-major [m][k] pad36, Bs row-major [k][n] pad132 -> conflict-free frags.
// ---------------------------------------------------------------------------
#define GAPAD 36
#define GBPAD 132

__global__ __launch_bounds__(256) void gemm_tf32(const float* __restrict__ A,
                                                 const float* __restrict__ B,
                                                 const float* __restrict__ bias,
                                                 float* __restrict__ C,
                                                 int M, int N, int K) {
    __shared__ unsigned As[128 * GAPAD];
    __shared__ unsigned Bs[32 * GBPAD];

    int t = threadIdx.x;
    int w = t >> 5;
    int lane = t & 31;
    int g = lane >> 2;
    int tig = lane & 3;
    int wm = w >> 1;      // 0..3
    int wn = w & 1;       // 0..1

    // staging coords
    int arow = t >> 3;          // 0..31 (+32*l)
    int acol = (t & 7) * 4;
    int brow = t >> 5;          // 0..7 (+8*l)
    int bcol = (t & 31) * 4;

    const float* Ag = A + (size_t)(blockIdx.y * 128 + arow) * K + acol;
    const float* Bg = B + (size_t)brow * N + blockIdx.x * 128 + bcol;

    float acc[2][8][4];
#pragma unroll
    for (int im = 0; im < 2; im++)
#pragma unroll
        for (int nt = 0; nt < 8; nt++)
#pragma unroll
            for (int e = 0; e < 4; e++) acc[im][nt][e] = 0.f;

    for (int k0 = 0; k0 < K; k0 += 32) {
        float4 av[4], bv[4];
#pragma unroll
        for (int l = 0; l < 4; l++) av[l] = *(const float4*)(Ag + (size_t)(l * 32) * K);
#pragma unroll
        for (int l = 0; l < 4; l++) bv[l] = *(const float4*)(Bg + (size_t)(l * 8) * N);
        __syncthreads();
#pragma unroll
        for (int l = 0; l < 4; l++) {
            uint4 u;
            u.x = f2tf(av[l].x); u.y = f2tf(av[l].y);
            u.z = f2tf(av[l].z); u.w = f2tf(av[l].w);
            *(uint4*)&As[(arow + l * 32) * GAPAD + acol] = u;
            uint4 v;
            v.x = f2tf(bv[l].x); v.y = f2tf(bv[l].y);
            v.z = f2tf(bv[l].z); v.w = f2tf(bv[l].w);
            *(uint4*)&Bs[(brow + l * 8) * GBPAD + bcol] = v;
        }
        __syncthreads();

#pragma unroll
        for (int kk = 0; kk < 4; kk++) {
            unsigned a[2][4];
#pragma unroll
            for (int im = 0; im < 2; im++) {
                int r = wm * 32 + im * 16 + g;
                a[im][0] = As[r * GAPAD + kk * 8 + tig];
                a[im][1] = As[(r + 8) * GAPAD + kk * 8 + tig];
                a[im][2] = As[r * GAPAD + kk * 8 + tig + 4];
                a[im][3] = As[(r + 8) * GAPAD + kk * 8 + tig + 4];
            }
#pragma unroll
            for (int nt = 0; nt < 8; nt++) {
                unsigned b[2];
                int cn = wn * 64 + nt * 8 + g;
                b[0] = Bs[(kk * 8 + tig) * GBPAD + cn];
                b[1] = Bs[(kk * 8 + tig + 4) * GBPAD + cn];
                mma_tf32(acc[0][nt], a[0], b);
                mma_tf32(acc[1][nt], a[1], b);
            }
        }
        Ag += 32;
        Bg += (size_t)32 * N;
    }

    // epilogue
#pragma unroll
    for (int im = 0; im < 2; im++) {
        int row = blockIdx.y * 128 + wm * 32 + im * 16 + g;
#pragma unroll
        for (int nt = 0; nt < 8; nt++) {
            int col = blockIdx.x * 128 + wn * 64 + nt * 8 + tig * 2;
            float b0 = bias ? bias[col] : 0.f;
            float b1 = bias ? bias[col + 1] : 0.f;
            float2 v0 = make_float2(acc[im][nt][0] + b0, acc[im][nt][1] + b1);
            float2 v1 = make_float2(acc[im][nt][2] + b0, acc[im][nt][3] + b1);
            *(float2*)&C[(size_t)row * N + col] = v0;
            *(float2*)&C[(size_t)(row + 8) * N + col] = v1;
        }
    }
}

// ---------------------------------------------------------------------------
// Flash attention (tf32 tensor core). Block: 256 thr / 8 warps.
// q-tile 128 rows (16 per warp), kv-tile 64, hd=64. Online softmax in regs.
// smem row-major, pad 68 -> conflict-free fragment loads, no transposes.
// Q scale 1/8 folded into its tf32 staging.
// ---------------------------------------------------------------------------
#define FP 68
#define FLASH_SMEM ((128 * FP + 64 * FP + 64 * FP + 128 * FP) * 4)

__global__ __launch_bounds__(256) void flash_tf32(const float* __restrict__ Qg,
                                                  const float* __restrict__ Kg,
                                                  const float* __restrict__ Vg,
                                                  float* __restrict__ Og) {
    extern __shared__ unsigned sm[];
    unsigned* Qs = sm;               // [128][FP]
    unsigned* Ks = Qs + 128 * FP;    // [64][FP]
    unsigned* Vs = Ks + 64 * FP;     // [64][FP]
    unsigned* Ps = Vs + 64 * FP;     // [128][FP]

    int t = threadIdx.x;
    int w = t >> 5;
    int lane = t & 31;
    int g = lane >> 2;
    int tig = lane & 3;

    int qt = blockIdx.x;
    int bh = blockIdx.y;
    int b = bh >> 4;
    int h = bh & 15;
    int qRowBase = b * TT + qt * 128;
    int colBase = h * HD;

    // stage Q (scaled by 0.125)
    {
        int r = t >> 4;
        int c4 = (t & 15) * 4;
#pragma unroll
        for (int l = 0; l < 8; l++) {
            int rr = r + l * 16;
            float4 v = *(const float4*)&Qg[(size_t)(qRowBase + rr) * DD + colBase + c4];
            uint4 u;
            u.x = f2tf(v.x * 0.125f); u.y = f2tf(v.y * 0.125f);
            u.z = f2tf(v.z * 0.125f); u.w = f2tf(v.w * 0.125f);
            *(uint4*)&Qs[rr * FP + c4] = u;
        }
    }

    float m0 = -INFINITY, m1 = -INFINITY, l0 = 0.f, l1 = 0.f;
    float o[8][4];
#pragma unroll
    for (int nt = 0; nt < 8; nt++)
#pragma unroll
        for (int e = 0; e < 4; e++) o[nt][e] = 0.f;

    int myRow0 = w * 16 + g;       // this thread's q rows (and +8)

    for (int j = 0; j < TT / 64; j++) {
        __syncthreads();
        // stage K, V tiles (64 x 64)
        {
            int r = t >> 4;
            int c4 = (t & 15) * 4;
            int kvBase = b * TT + j * 64;
#pragma unroll
            for (int l = 0; l < 4; l++) {
                int rr = r + l * 16;
                float4 kv = *(const float4*)&Kg[(size_t)(kvBase + rr) * DD + colBase + c4];
                uint4 uk;
                uk.x = f2tf(kv.x); uk.y = f2tf(kv.y); uk.z = f2tf(kv.z); uk.w = f2tf(kv.w);
                *(uint4*)&Ks[rr * FP + c4] = uk;
                float4 vv = *(const float4*)&Vg[(size_t)(kvBase + rr) * DD + colBase + c4];
                uint4 uv;
                uv.x = f2tf(vv.x); uv.y = f2tf(vv.y); uv.z = f2tf(vv.z); uv.w = f2tf(vv.w);
                *(uint4*)&Vs[rr * FP + c4] = uv;
            }
        }
        __syncthreads();

        // S = Qs @ Ks^T  (warp: 16 rows x 64 kv cols)
        float s[8][4];
#pragma unroll
        for (int nt = 0; nt < 8; nt++)
#pragma unroll
            for (int e = 0; e < 4; e++) s[nt][e] = 0.f;
#pragma unroll
        for (int kk = 0; kk < 8; kk++) {
            unsigned a[4];
            a[0] = Qs[myRow0 * FP + kk * 8 + tig];
            a[1] = Qs[(myRow0 + 8) * FP + kk * 8 + tig];
            a[2] = Qs[myRow0 * FP + kk * 8 + tig + 4];
            a[3] = Qs[(myRow0 + 8) * FP + kk * 8 + tig + 4];
#pragma unroll
            for (int nt = 0; nt < 8; nt++) {
                unsigned bb[2];
                bb[0] = Ks[(nt * 8 + g) * FP + kk * 8 + tig];
                bb[1] = Ks[(nt * 8 + g) * FP + kk * 8 + tig + 4];
                mma_tf32(s[nt], a, bb);
            }
        }

        // online softmax (rows myRow0, myRow0+8)
        float mt0 = -INFINITY, mt1 = -INFINITY;
#pragma unroll
        for (int nt = 0; nt < 8; nt++) {
            mt0 = fmaxf(mt0, fmaxf(s[nt][0], s[nt][1]));
            mt1 = fmaxf(mt1, fmaxf(s[nt][2], s[nt][3]));
        }
        mt0 = fmaxf(mt0, __shfl_xor_sync(0xffffffffu, mt0, 1));
        mt0 = fmaxf(mt0, __shfl_xor_sync(0xffffffffu, mt0, 2));
        mt1 = fmaxf(mt1, __shfl_xor_sync(0xffffffffu, mt1, 1));
        mt1 = fmaxf(mt1, __shfl_xor_sync(0xffffffffu, mt1, 2));

        float mn0 = fmaxf(m0, mt0);
        float mn1 = fmaxf(m1, mt1);
        float alpha0 = __expf(m0 - mn0);
        float alpha1 = __expf(m1 - mn1);
        m0 = mn0; m1 = mn1;

        float rs0 = 0.f, rs1 = 0.f;
#pragma unroll
        for (int nt = 0; nt < 8; nt++) {
            float p00 = __expf(s[nt][0] - mn0);
            float p01 = __expf(s[nt][1] - mn0);
            float p10 = __expf(s[nt][2] - mn1);
            float p11 = __expf(s[nt][3] - mn1);
            rs0 += p00 + p01;
            rs1 += p10 + p11;
            int col = nt * 8 + 2 * tig;
            uint2 u0 = make_uint2(f2tf(p00), f2tf(p01));
            uint2 u1 = make_uint2(f2tf(p10), f2tf(p11));
            *(uint2*)&Ps[myRow0 * FP + col] = u0;
            *(uint2*)&Ps[(myRow0 + 8) * FP + col] = u1;
        }
        rs0 += __shfl_xor_sync(0xffffffffu, rs0, 1);
        rs0 += __shfl_xor_sync(0xffffffffu, rs0, 2);
        rs1 += __shfl_xor_sync(0xffffffffu, rs1, 1);
        rs1 += __shfl_xor_sync(0xffffffffu, rs1, 2);
        l0 = alpha0 * l0 + rs0;
        l1 = alpha1 * l1 + rs1;

        // rescale O accumulators
#pragma unroll
        for (int nt = 0; nt < 8; nt++) {
            o[nt][0] *= alpha0; o[nt][1] *= alpha0;
            o[nt][2] *= alpha1; o[nt][3] *= alpha1;
        }

        __syncwarp();

        // O += P @ V  (k-dim = 64 kv)
#pragma unroll
        for (int kk = 0; kk < 8; kk++) {
            unsigned a[4];
            a[0] = Ps[myRow0 * FP + kk * 8 + tig];
            a[1] = Ps[(myRow0 + 8) * FP + kk * 8 + tig];
            a[2] = Ps[myRow0 * FP + kk * 8 + tig + 4];
            a[3] = Ps[(myRow0 + 8) * FP + kk * 8 + tig + 4];
#pragma unroll
            for (int nt = 0; nt < 8; nt++) {
                unsigned bb[2];
                bb[0] = Vs[(kk * 8 + tig) * FP + nt * 8 + g];
                bb[1] = Vs[(kk * 8 + tig + 4) * FP + nt * 8 + g];
                mma_tf32(o[nt], a, bb);
            }
        }
        __syncwarp();
    }

    // epilogue
    float invl0 = 1.f / l0;
    float invl1 = 1.f / l1;
    int row0 = qRowBase + myRow0;
#pragma unroll
    for (int nt = 0; nt < 8; nt++) {
        int col = colBase + nt * 8 + 2 * tig;
        float2 v0 = make_float2(o[nt][0] * invl0, o[nt][1] * invl0);
        float2 v1 = make_float2(o[nt][2] * invl1, o[nt][3] * invl1);
        *(float2*)&Og[(size_t)row0 * DD + col] = v0;
        *(float2*)&Og[(size_t)(row0 + 8) * DD + col] = v1;
    }
}

// ---------------------------------------------------------------------------
extern "C" void kernel_launch(void* const* d_in, const int* in_sizes, int n_in,
                              void* d_out, int out_size) {
    (void)in_sizes; (void)n_in; (void)out_size;
    const float* x  = (const float*)d_in[0];
    const float* Wq = (const float*)d_in[1];
    const float* Wk = (const float*)d_in[2];
    const float* Wv = (const float*)d_in[3];
    const float* Wo = (const float*)d_in[4];
    const float* bo = (const float*)d_in[5];
    float* out = (float*)d_out;

    float *Q, *K, *V, *O, *rope, *Mm, *Wv2;
    cudaGetSymbolAddress((void**)&Q, g_Q);
    cudaGetSymbolAddress((void**)&K, g_K);
    cudaGetSymbolAddress((void**)&V, g_V);
    cudaGetSymbolAddress((void**)&O, g_O);
    cudaGetSymbolAddress((void**)&rope, g_rope);
    cudaGetSymbolAddress((void**)&Mm, g_M);
    cudaGetSymbolAddress((void**)&Wv2, g_Wv2);

    rope_kernel<<<TT, HD>>>(rope);
    m_kernel<<<HD, HD>>>(rope, Mm);
    fold_wv_kernel<<<(DD * DD) / 256, 256>>>(Wv, Mm, Wv2);

    dim3 ggrid(DD / 128, MROWS / 128);  // (8, 32)
    gemm_tf32<<<ggrid, 256>>>(x, Wq, nullptr, Q, MROWS, DD, DD);
    gemm_tf32<<<ggrid, 256>>>(x, Wk, nullptr, K, MROWS, DD, DD);
    gemm_tf32<<<ggrid, 256>>>(x, Wv2, nullptr, V, MROWS, DD, DD);

    cudaFuncSetAttribute(flash_tf32, cudaFuncAttributeMaxDynamicSharedMemorySize,
                         FLASH_SMEM);
    flash_tf32<<<dim3(TT / 128, BB * HH), 256, FLASH_SMEM>>>(Q, K, V, O);

    gemm_tf32<<<ggrid, 256>>>(O, Wo, bo, out, MROWS, DD, DD);
}

// round 7
// speedup vs baseline: 5.5741x; 2.0106x over previous
#include <cuda_runtime.h>
#include <cuda_fp16.h>
#include <math.h>

// ---------------------------------------------------------------------------
// B=2, T=2048, D=1024, H=16, hd=64
// out = softmax(QK^T/8) @ V @ (rope^T rope) -> fold M into Wv.
// fp16 mma.sync m16n8k16 + ldmatrix + cp.async pipelines.
// ---------------------------------------------------------------------------
#define BB 2
#define TT 2048
#define DD 1024
#define HH 16
#define HD 64
#define MROWS (BB * TT)   // 4096

__device__ __align__(16) __half g_xh[MROWS * DD];
__device__ __align__(16) __half g_Wqh[DD * DD];
__device__ __align__(16) __half g_Wkh[DD * DD];
__device__ __align__(16) __half g_Wvh[DD * DD];
__device__ __align__(16) __half g_Woh[DD * DD];
__device__ __align__(16) __half g_Qh[MROWS * DD];
__device__ __align__(16) __half g_Kh[MROWS * DD];
__device__ __align__(16) __half g_Vh[MROWS * DD];
__device__ __align__(16) __half g_Oh[MROWS * DD];
__device__ float g_rope[TT * HD];
__device__ float g_M[HD * HD];
__device__ float g_Wv2[DD * DD];

// ---------------------------------------------------------------------------
__device__ __forceinline__ unsigned h2(float lo, float hi) {
    unsigned r;
    asm("cvt.rn.f16x2.f32 %0, %1, %2;" : "=r"(r) : "f"(hi), "f"(lo));
    return r;
}

__device__ __forceinline__ void mma_f16(float* c, const unsigned* a, unsigned b0, unsigned b1) {
    asm volatile(
        "mma.sync.aligned.m16n8k16.row.col.f32.f16.f16.f32 "
        "{%0,%1,%2,%3}, {%4,%5,%6,%7}, {%8,%9}, {%0,%1,%2,%3};"
        : "+f"(c[0]), "+f"(c[1]), "+f"(c[2]), "+f"(c[3])
        : "r"(a[0]), "r"(a[1]), "r"(a[2]), "r"(a[3]), "r"(b0), "r"(b1));
}

__device__ __forceinline__ void ldsm4(unsigned* r, unsigned addr) {
    asm volatile("ldmatrix.sync.aligned.m8n8.x4.shared.b16 {%0,%1,%2,%3}, [%4];"
                 : "=r"(r[0]), "=r"(r[1]), "=r"(r[2]), "=r"(r[3]) : "r"(addr));
}

__device__ __forceinline__ void ldsm4t(unsigned* r, unsigned addr) {
    asm volatile("ldmatrix.sync.aligned.m8n8.x4.trans.shared.b16 {%0,%1,%2,%3}, [%4];"
                 : "=r"(r[0]), "=r"(r[1]), "=r"(r[2]), "=r"(r[3]) : "r"(addr));
}

#define CPA16(dst, src) \
    asm volatile("cp.async.cg.shared.global [%0], [%1], 16;" :: "r"(dst), "l"(src))
#define CP_COMMIT() asm volatile("cp.async.commit_group;")
#define CP_WAIT0()  asm volatile("cp.async.wait_group 0;")

// ---------------------------------------------------------------------------
// Prologue kernels
// ---------------------------------------------------------------------------
__global__ void rope_kernel(float* __restrict__ rope) {
    int s = blockIdx.x;
    int d = threadIdx.x;
    int dd = (d < 32) ? d : d - 32;
    double invf = exp(-((double)dd / 32.0) * log(10000.0));
    float ang = (float)s * (float)invf;
    double a = (double)ang;
    rope[s * HD + d] = (d < 32) ? (float)cos(a) : (float)sin(a);
}

__global__ void m_kernel(const float* __restrict__ rope, float* __restrict__ Mm) {
    int i = blockIdx.x;
    int j = threadIdx.x;
    float acc = 0.f;
    for (int s = 0; s < TT; s++)
        acc += rope[s * HD + i] * rope[s * HD + j];
    Mm[i * HD + j] = acc;
}

__global__ void fold_wv_kernel(const float* __restrict__ Wv,
                               const float* __restrict__ Mm,
                               float* __restrict__ Wv2) {
    __shared__ float Ms[HD * HD];
    for (int t = threadIdx.x; t < HD * HD; t += 256) Ms[t] = Mm[t];
    __syncthreads();
    int idx = blockIdx.x * 256 + threadIdx.x;
    int r = idx >> 10;
    int c = idx & 1023;
    int hh = c >> 6;
    int j = c & 63;
    const float* w = Wv + r * DD + hh * HD;
    float acc = 0.f;
#pragma unroll 16
    for (int i = 0; i < HD; i++)
        acc += w[i] * Ms[i * HD + j];
    Wv2[idx] = acc;
}

__global__ void cvt_kernel(const float* __restrict__ in, __half* __restrict__ out, int n4) {
    int i = blockIdx.x * blockDim.x + threadIdx.x;
    if (i < n4) {
        float4 v = ((const float4*)in)[i];
        uint2 u;
        u.x = h2(v.x, v.y);
        u.y = h2(v.z, v.w);
        ((uint2*)out)[i] = u;
    }
}

// ---------------------------------------------------------------------------
// fp16 GEMM: C[M,N] = alpha * (A@B) + bias. A,B f16; C f32 or f16.
// Block 128x128, BK=32, 256 thr / 8 warps (4m x 2n), warp tile 32x64.
// As [m][k] stride 40 halves (80B = 5x16B odd), Bs [k][n] stride 136 (17x16B).
// 2-stage cp.async pipeline, ldmatrix fragment loads.
// ---------------------------------------------------------------------------
#define AST 40
#define BST 136

__global__ __launch_bounds__(256) void gemm_f16(const __half* __restrict__ A,
                                                const __half* __restrict__ B,
                                                const float* __restrict__ bias,
                                                float* __restrict__ Cf,
                                                __half* __restrict__ Ch,
                                                float alpha,
                                                int M, int N, int K) {
    __shared__ __half As[2][128 * AST];
    __shared__ __half Bs[2][32 * BST];

    int t = threadIdx.x;
    int lane = t & 31;
    int w = t >> 5;
    int g = lane >> 2;
    int tig = lane & 3;
    int wm = w >> 1;
    int wn = w & 1;
    int jm = (lane >> 3) & 1;
    int jk = lane >> 4;
    int jr = lane & 7;

    int m0 = blockIdx.y * 128;
    int n0 = blockIdx.x * 128;

    unsigned asB[2], bsB[2];
    asB[0] = (unsigned)__cvta_generic_to_shared(&As[0][0]);
    asB[1] = (unsigned)__cvta_generic_to_shared(&As[1][0]);
    bsB[0] = (unsigned)__cvta_generic_to_shared(&Bs[0][0]);
    bsB[1] = (unsigned)__cvta_generic_to_shared(&Bs[1][0]);

    // staging coords
    int arow = t >> 2;          // 0..63, +64
    int aslot = t & 3;
    int brow = t >> 4;          // 0..15, +16
    int bslot = t & 15;
    unsigned aDst = (unsigned)(arow * AST + aslot * 8) * 2;
    unsigned bDst = (unsigned)(brow * BST + bslot * 8) * 2;

    float acc[2][8][4];
#pragma unroll
    for (int im = 0; im < 2; im++)
#pragma unroll
        for (int nt = 0; nt < 8; nt++)
#pragma unroll
            for (int e = 0; e < 4; e++) acc[im][nt][e] = 0.f;

    // prologue: stage k0=0 into buf 0
    {
        CPA16(asB[0] + aDst, A + (size_t)(m0 + arow) * K + aslot * 8);
        CPA16(asB[0] + aDst + 64 * AST * 2, A + (size_t)(m0 + arow + 64) * K + aslot * 8);
        CPA16(bsB[0] + bDst, B + (size_t)brow * N + n0 + bslot * 8);
        CPA16(bsB[0] + bDst + 16 * BST * 2, B + (size_t)(brow + 16) * N + n0 + bslot * 8);
        CP_COMMIT();
    }

    unsigned aoff = (unsigned)((wm * 32 + jm * 8 + jr) * AST + jk * 8) * 2;
    unsigned boff = (unsigned)((jm * 8 + jr) * BST + wn * 64 + jk * 8) * 2;

    int NI = K / 32;
    for (int i = 0; i < NI; i++) {
        CP_WAIT0();
        __syncthreads();
        if (i + 1 < NI) {
            int k0 = (i + 1) * 32;
            int s = (i + 1) & 1;
            CPA16(asB[s] + aDst, A + (size_t)(m0 + arow) * K + k0 + aslot * 8);
            CPA16(asB[s] + aDst + 64 * AST * 2, A + (size_t)(m0 + arow + 64) * K + k0 + aslot * 8);
            CPA16(bsB[s] + bDst, B + (size_t)(k0 + brow) * N + n0 + bslot * 8);
            CPA16(bsB[s] + bDst + 16 * BST * 2, B + (size_t)(k0 + brow + 16) * N + n0 + bslot * 8);
            CP_COMMIT();
        }
        int s = i & 1;
#pragma unroll
        for (int kk = 0; kk < 2; kk++) {
            unsigned af[2][4];
#pragma unroll
            for (int im = 0; im < 2; im++)
                ldsm4(af[im], asB[s] + aoff + (unsigned)(im * 16 * AST + kk * 16) * 2);
#pragma unroll
            for (int p = 0; p < 4; p++) {
                unsigned bf[4];
                ldsm4t(bf, bsB[s] + boff + (unsigned)(kk * 16 * BST + p * 16) * 2);
                mma_f16(acc[0][2 * p], af[0], bf[0], bf[1]);
                mma_f16(acc[1][2 * p], af[1], bf[0], bf[1]);
                mma_f16(acc[0][2 * p + 1], af[0], bf[2], bf[3]);
                mma_f16(acc[1][2 * p + 1], af[1], bf[2], bf[3]);
            }
        }
    }

    // epilogue
#pragma unroll
    for (int im = 0; im < 2; im++) {
        int row = m0 + wm * 32 + im * 16 + g;
#pragma unroll
        for (int nt = 0; nt < 8; nt++) {
            int col = n0 + wn * 64 + nt * 8 + tig * 2;
            float b0 = bias ? bias[col] : 0.f;
            float b1 = bias ? bias[col + 1] : 0.f;
            float c0 = acc[im][nt][0] * alpha + b0;
            float c1 = acc[im][nt][1] * alpha + b1;
            float c2 = acc[im][nt][2] * alpha + b0;
            float c3 = acc[im][nt][3] * alpha + b1;
            if (Cf) {
                *(float2*)&Cf[(size_t)row * N + col] = make_float2(c0, c1);
                *(float2*)&Cf[(size_t)(row + 8) * N + col] = make_float2(c2, c3);
            } else {
                *(unsigned*)&Ch[(size_t)row * N + col] = h2(c0, c1);
                *(unsigned*)&Ch[(size_t)(row + 8) * N + col] = h2(c2, c3);
            }
        }
    }
}

// ---------------------------------------------------------------------------
// Flash attention fp16. Block 256 thr / 8 warps; q-tile 128 (16 rows/warp),
// kv-tile 64, hd=64. Q frags in registers; P stays in registers (C-frag ==
// next A-frag layout). K/V double-buffered via cp.async. Output f16.
// Q already scaled by 1/8 (folded into Q-projection GEMM alpha).
// ---------------------------------------------------------------------------
#define QST 72
#define KST 72
#define FLASH_SMEM ((128 * QST + 4 * 64 * KST) * 2)

__global__ __launch_bounds__(256) void flash_f16(const __half* __restrict__ Qg,
                                                 const __half* __restrict__ Kg,
                                                 const __half* __restrict__ Vg,
                                                 __half* __restrict__ Og) {
    extern __shared__ __half sm[];
    __half* Qs = sm;                       // [128][QST]
    __half* Ks0 = Qs + 128 * QST;          // [64][KST] x2 stages
    __half* Vs0 = Ks0 + 2 * 64 * KST;      // [64][KST] x2 stages

    int t = threadIdx.x;
    int lane = t & 31;
    int w = t >> 5;
    int g = lane >> 2;
    int tig = lane & 3;
    int jm = (lane >> 3) & 1;
    int jk = lane >> 4;
    int jr = lane & 7;

    int qt = blockIdx.x;
    int bh = blockIdx.y;
    int b = bh >> 4;
    int h = bh & 15;
    int qRowBase = b * TT + qt * 128;
    int colBase = h * HD;

    unsigned qsB = (unsigned)__cvta_generic_to_shared(Qs);
    unsigned ksB[2], vsB[2];
    ksB[0] = (unsigned)__cvta_generic_to_shared(Ks0);
    ksB[1] = ksB[0] + 64 * KST * 2;
    vsB[0] = (unsigned)__cvta_generic_to_shared(Vs0);
    vsB[1] = vsB[0] + 64 * KST * 2;

    // KV staging coords: rows 0..63 (t>>3, +32), slot = t&7 (8 halves)
    int kvrow = t >> 3;
    int kvslot = t & 7;
    unsigned kvDst = (unsigned)(kvrow * KST + kvslot * 8) * 2;

    // issue KV stage 0
    {
        int kvBase = b * TT;
        CPA16(ksB[0] + kvDst, Kg + (size_t)(kvBase + kvrow) * DD + colBase + kvslot * 8);
        CPA16(ksB[0] + kvDst + 32 * KST * 2, Kg + (size_t)(kvBase + kvrow + 32) * DD + colBase + kvslot * 8);
        CPA16(vsB[0] + kvDst, Vg + (size_t)(kvBase + kvrow) * DD + colBase + kvslot * 8);
        CPA16(vsB[0] + kvDst + 32 * KST * 2, Vg + (size_t)(kvBase + kvrow + 32) * DD + colBase + kvslot * 8);
        CP_COMMIT();
    }

    // copy Q tile (128 x 64 halves) into smem
    {
#pragma unroll
        for (int l = 0; l < 4; l++) {
            int u = t + 256 * l;
            int row = u >> 3;
            int slot = u & 7;
            uint4 v = *(const uint4*)&Qg[(size_t)(qRowBase + row) * DD + colBase + slot * 8];
            *(uint4*)&Qs[row * QST + slot * 8] = v;
        }
    }
    __syncthreads();

    // load Q fragments (persistent)
    unsigned qf[4][4];
    {
        unsigned qoff = (unsigned)((w * 16 + jm * 8 + jr) * QST + jk * 8) * 2;
#pragma unroll
        for (int kk = 0; kk < 4; kk++)
            ldsm4(qf[kk], qsB + qoff + (unsigned)(kk * 16) * 2);
    }

    float m0 = -INFINITY, m1 = -INFINITY, l0 = 0.f, l1 = 0.f;
    float o[8][4];
#pragma unroll
    for (int nt = 0; nt < 8; nt++)
#pragma unroll
        for (int e = 0; e < 4; e++) o[nt][e] = 0.f;

    unsigned koff = (unsigned)((jk * 8 + jr) * KST + jm * 8) * 2;  // K: row=kv, col=d
    unsigned voff = (unsigned)((jm * 8 + jr) * KST + jk * 8) * 2;  // V: row=kv(k), col=d(n)

    for (int j = 0; j < TT / 64; j++) {
        CP_WAIT0();
        __syncthreads();
        if (j + 1 < TT / 64) {
            int kvBase = b * TT + (j + 1) * 64;
            int s = (j + 1) & 1;
            CPA16(ksB[s] + kvDst, Kg + (size_t)(kvBase + kvrow) * DD + colBase + kvslot * 8);
            CPA16(ksB[s] + kvDst + 32 * KST * 2, Kg + (size_t)(kvBase + kvrow + 32) * DD + colBase + kvslot * 8);
            CPA16(vsB[s] + kvDst, Vg + (size_t)(kvBase + kvrow) * DD + colBase + kvslot * 8);
            CPA16(vsB[s] + kvDst + 32 * KST * 2, Vg + (size_t)(kvBase + kvrow + 32) * DD + colBase + kvslot * 8);
            CP_COMMIT();
        }
        int s = j & 1;

        // S = Q @ K^T
        float sc[8][4];
#pragma unroll
        for (int nt = 0; nt < 8; nt++)
#pragma unroll
            for (int e = 0; e < 4; e++) sc[nt][e] = 0.f;
#pragma unroll
        for (int kk = 0; kk < 4; kk++) {
#pragma unroll
            for (int p = 0; p < 4; p++) {
                unsigned kf[4];
                ldsm4(kf, ksB[s] + koff + (unsigned)(p * 16 * KST + kk * 16) * 2);
                mma_f16(sc[2 * p], qf[kk], kf[0], kf[1]);
                mma_f16(sc[2 * p + 1], qf[kk], kf[2], kf[3]);
            }
        }

        // online softmax
        float mt0 = -INFINITY, mt1 = -INFINITY;
#pragma unroll
        for (int nt = 0; nt < 8; nt++) {
            mt0 = fmaxf(mt0, fmaxf(sc[nt][0], sc[nt][1]));
            mt1 = fmaxf(mt1, fmaxf(sc[nt][2], sc[nt][3]));
        }
        mt0 = fmaxf(mt0, __shfl_xor_sync(0xffffffffu, mt0, 1));
        mt0 = fmaxf(mt0, __shfl_xor_sync(0xffffffffu, mt0, 2));
        mt1 = fmaxf(mt1, __shfl_xor_sync(0xffffffffu, mt1, 1));
        mt1 = fmaxf(mt1, __shfl_xor_sync(0xffffffffu, mt1, 2));

        float mn0 = fmaxf(m0, mt0);
        float mn1 = fmaxf(m1, mt1);
        float alpha0 = __expf(m0 - mn0);
        float alpha1 = __expf(m1 - mn1);
        m0 = mn0;
        m1 = mn1;

        unsigned pf[4][4];
        float rs0 = 0.f, rs1 = 0.f;
#pragma unroll
        for (int nt = 0; nt < 8; nt++) {
            float p0 = __expf(sc[nt][0] - mn0);
            float p1 = __expf(sc[nt][1] - mn0);
            float p2 = __expf(sc[nt][2] - mn1);
            float p3 = __expf(sc[nt][3] - mn1);
            rs0 += p0 + p1;
            rs1 += p2 + p3;
            pf[nt >> 1][(nt & 1) * 2] = h2(p0, p1);
            pf[nt >> 1][(nt & 1) * 2 + 1] = h2(p2, p3);
        }
        rs0 += __shfl_xor_sync(0xffffffffu, rs0, 1);
        rs0 += __shfl_xor_sync(0xffffffffu, rs0, 2);
        rs1 += __shfl_xor_sync(0xffffffffu, rs1, 1);
        rs1 += __shfl_xor_sync(0xffffffffu, rs1, 2);
        l0 = alpha0 * l0 + rs0;
        l1 = alpha1 * l1 + rs1;

#pragma unroll
        for (int nt = 0; nt < 8; nt++) {
            o[nt][0] *= alpha0;
            o[nt][1] *= alpha0;
            o[nt][2] *= alpha1;
            o[nt][3] *= alpha1;
        }

        // O += P @ V
#pragma unroll
        for (int kk2 = 0; kk2 < 4; kk2++) {
#pragma unroll
            for (int p = 0; p < 4; p++) {
                unsigned vf[4];
                ldsm4t(vf, vsB[s] + voff + (unsigned)(kk2 * 16 * KST + p * 16) * 2);
                mma_f16(o[2 * p], pf[kk2], vf[0], vf[1]);
                mma_f16(o[2 * p + 1], pf[kk2], vf[2], vf[3]);
            }
        }
    }

    // epilogue
    float invl0 = 1.f / l0;
    float invl1 = 1.f / l1;
    int row0 = qRowBase + w * 16 + g;
#pragma unroll
    for (int nt = 0; nt < 8; nt++) {
        int col = colBase + nt * 8 + 2 * tig;
        *(unsigned*)&Og[(size_t)row0 * DD + col] = h2(o[nt][0] * invl0, o[nt][1] * invl0);
        *(unsigned*)&Og[(size_t)(row0 + 8) * DD + col] = h2(o[nt][2] * invl1, o[nt][3] * invl1);
    }
}

// ---------------------------------------------------------------------------
extern "C" void kernel_launch(void* const* d_in, const int* in_sizes, int n_in,
                              void* d_out, int out_size) {
    (void)in_sizes; (void)n_in; (void)out_size;
    const float* x  = (const float*)d_in[0];
    const float* Wq = (const float*)d_in[1];
    const float* Wk = (const float*)d_in[2];
    const float* Wv = (const float*)d_in[3];
    const float* Wo = (const float*)d_in[4];
    const float* bo = (const float*)d_in[5];
    float* out = (float*)d_out;

    float *rope, *Mm, *Wv2;
    __half *xh, *Wqh, *Wkh, *Wvh, *Woh, *Qh, *Kh, *Vh, *Oh;
    cudaGetSymbolAddress((void**)&rope, g_rope);
    cudaGetSymbolAddress((void**)&Mm, g_M);
    cudaGetSymbolAddress((void**)&Wv2, g_Wv2);
    cudaGetSymbolAddress((void**)&xh, g_xh);
    cudaGetSymbolAddress((void**)&Wqh, g_Wqh);
    cudaGetSymbolAddress((void**)&Wkh, g_Wkh);
    cudaGetSymbolAddress((void**)&Wvh, g_Wvh);
    cudaGetSymbolAddress((void**)&Woh, g_Woh);
    cudaGetSymbolAddress((void**)&Qh, g_Qh);
    cudaGetSymbolAddress((void**)&Kh, g_Kh);
    cudaGetSymbolAddress((void**)&Vh, g_Vh);
    cudaGetSymbolAddress((void**)&Oh, g_Oh);

    rope_kernel<<<TT, HD>>>(rope);
    m_kernel<<<HD, HD>>>(rope, Mm);
    fold_wv_kernel<<<(DD * DD) / 256, 256>>>(Wv, Mm, Wv2);

    // convert inputs to f16
    cvt_kernel<<<(MROWS * DD / 4 + 255) / 256, 256>>>(x, xh, MROWS * DD / 4);
    cvt_kernel<<<(DD * DD / 4 + 255) / 256, 256>>>(Wq, Wqh, DD * DD / 4);
    cvt_kernel<<<(DD * DD / 4 + 255) / 256, 256>>>(Wk, Wkh, DD * DD / 4);
    cvt_kernel<<<(DD * DD / 4 + 255) / 256, 256>>>(Wv2, Wvh, DD * DD / 4);
    cvt_kernel<<<(DD * DD / 4 + 255) / 256, 256>>>(Wo, Woh, DD * DD / 4);

    dim3 ggrid(DD / 128, MROWS / 128);  // (8, 32)
    // Q scaled by 1/8 here (softmax scale folded in)
    gemm_f16<<<ggrid, 256>>>(xh, Wqh, nullptr, nullptr, Qh, 0.125f, MROWS, DD, DD);
    gemm_f16<<<ggrid, 256>>>(xh, Wkh, nullptr, nullptr, Kh, 1.0f, MROWS, DD, DD);
    gemm_f16<<<ggrid, 256>>>(xh, Wvh, nullptr, nullptr, Vh, 1.0f, MROWS, DD, DD);

    cudaFuncSetAttribute(flash_f16, cudaFuncAttributeMaxDynamicSharedMemorySize,
                         FLASH_SMEM);
    flash_f16<<<dim3(TT / 128, BB * HH), 256, FLASH_SMEM>>>(Qh, Kh, Vh, Oh);

    gemm_f16<<<ggrid, 256>>>(Oh, Woh, bo, out, nullptr, 1.0f, MROWS, DD, DD);
}